// round 15
// baseline (speedup 1.0000x reference)
#include <cuda_runtime.h>
#include <cuda_fp16.h>
#include <math.h>
#include <stdint.h>

#define BB  2
#define TT  2048
#define DM  2048
#define NH  32
#define NKV 8
#define DH  64
#define BT  (BB*TT)
#define KVD (NKV*DH)   /* 512 */
#define NC  (DM + 2*KVD)   /* 3072 combined output cols */

#define S_X    4096.f          /* 2^12 */
#define S_W    262144.f        /* 2^18 */
#define INV_SC (1.f / 1073741824.f)   /* 2^-30 */

// ---------------- scratch (device globals; no allocations allowed) ----------
__device__ int8_t g_x8h[(size_t)BT * DM],  g_x8l[(size_t)BT * DM];
__device__ int8_t g_Wc8h[(size_t)NC * DM], g_Wc8l[(size_t)NC * DM]; // Wq|Wk|Wv

__device__ half g_Wo[(size_t)DM * DM];                            // Wo * 64 single
__device__ half g_Ah[(size_t)BT * DM];                            // attn out x16 single

__device__ half g_Qh[(size_t)BT * DM];                            // roped, x0.125 single
__device__ half g_Kh[(size_t)BT * KVD];                           // roped, single
__device__ half g_Vth[(size_t)BT * KVD];                          // (b,g,d,t) single

__device__ float g_cos[TT * 32];
__device__ float g_sin[TT * 32];

// ===================== helpers ======================
__device__ __forceinline__ uint32_t smem_u32(const void* p) {
    uint32_t a;
    asm("{ .reg .u64 t; cvta.to.shared.u64 t, %1; cvt.u32.u64 %0, t; }"
        : "=r"(a) : "l"(p));
    return a;
}

#define CP16(dst, src) \
    asm volatile("cp.async.cg.shared.global [%0], [%1], 16;" \
                 :: "r"(dst), "l"(src) : "memory")
#define CPCOMMIT() asm volatile("cp.async.commit_group;" ::: "memory")
#define CPWAIT(n)  asm volatile("cp.async.wait_group %0;" :: "n"(n) : "memory")

__device__ __forceinline__ void ldmx4(uint32_t& r0, uint32_t& r1,
                                      uint32_t& r2, uint32_t& r3, uint32_t a) {
    asm volatile("ldmatrix.sync.aligned.m8n8.x4.shared.b16 {%0,%1,%2,%3}, [%4];"
                 : "=r"(r0), "=r"(r1), "=r"(r2), "=r"(r3) : "r"(a));
}

__device__ __forceinline__ void mma16816(float* d, const uint32_t* a,
                                         const uint32_t* b) {
    asm volatile(
        "mma.sync.aligned.m16n8k16.row.col.f32.f16.f16.f32 "
        "{%0,%1,%2,%3},{%4,%5,%6,%7},{%8,%9},{%0,%1,%2,%3};"
        : "+f"(d[0]), "+f"(d[1]), "+f"(d[2]), "+f"(d[3])
        : "r"(a[0]), "r"(a[1]), "r"(a[2]), "r"(a[3]), "r"(b[0]), "r"(b[1]));
}

__device__ __forceinline__ void mma_s8(int* d, const uint32_t* a,
                                       const uint32_t* b) {
    asm volatile(
        "mma.sync.aligned.m16n8k32.row.col.s32.s8.s8.s32 "
        "{%0,%1,%2,%3},{%4,%5,%6,%7},{%8,%9},{%0,%1,%2,%3};"
        : "+r"(d[0]), "+r"(d[1]), "+r"(d[2]), "+r"(d[3])
        : "r"(a[0]), "r"(a[1]), "r"(a[2]), "r"(a[3]), "r"(b[0]), "r"(b[1]));
}

__device__ __forceinline__ uint32_t packh(float a, float b) {
    __half2 t = __floats2half2_rn(a, b);
    return *reinterpret_cast<uint32_t*>(&t);
}

// 16-bit fixed point -> two int8 digits (hi*256 + lo == q, exact)
__device__ __forceinline__ void qsplit(float v, float S, int8_t& hi, int8_t& lo) {
    int q = __float2int_rn(v * S);
    q = max(-32512, min(32512, q));
    int l = ((q + 128) & 255) - 128;
    hi = (int8_t)((q - l) >> 8);
    lo = (int8_t)l;
}

__device__ __forceinline__ float comb8(int hh, int mid) {
    return fmaf((float)hh, 65536.f, (float)mid * 256.f) * INV_SC;
}

// ---------------------------------------------------------------------------
// fused precompute: quant x | quant Wq/Wk/Wv | conv Wo | rope table
// ---------------------------------------------------------------------------
#define N_X (BT * DM / 4)
#define N_W (NC * DM / 4)
#define N_O (DM * DM / 4)
#define N_R (TT * 32)
#define N_PREP (N_X + N_W + N_O + N_R)

__global__ void prep_kernel(const float* __restrict__ x,
                            const float* __restrict__ Wq,
                            const float* __restrict__ Wk,
                            const float* __restrict__ Wv,
                            const float* __restrict__ Wo)
{
    int i = blockIdx.x * blockDim.x + threadIdx.x;
    if (i < N_X) {
        float4 v = ((const float4*)x)[i];
        int8_t h0, h1, h2, h3, l0, l1, l2, l3;
        qsplit(v.x, S_X, h0, l0);
        qsplit(v.y, S_X, h1, l1);
        qsplit(v.z, S_X, h2, l2);
        qsplit(v.w, S_X, h3, l3);
        ((char4*)g_x8h)[i] = make_char4(h0, h1, h2, h3);
        ((char4*)g_x8l)[i] = make_char4(l0, l1, l2, l3);
        return;
    }
    i -= N_X;
    if (i < N_W) {
        const int nq = DM * DM / 4;
        const int nk = KVD * DM / 4;
        const float* src;
        int si;
        if (i < nq)           { src = Wq; si = i; }
        else if (i < nq + nk) { src = Wk; si = i - nq; }
        else                  { src = Wv; si = i - nq - nk; }
        float4 v = ((const float4*)src)[si];
        int8_t h0, h1, h2, h3, l0, l1, l2, l3;
        qsplit(v.x, S_W, h0, l0);
        qsplit(v.y, S_W, h1, l1);
        qsplit(v.z, S_W, h2, l2);
        qsplit(v.w, S_W, h3, l3);
        ((char4*)g_Wc8h)[i] = make_char4(h0, h1, h2, h3);
        ((char4*)g_Wc8l)[i] = make_char4(l0, l1, l2, l3);
        return;
    }
    i -= N_W;
    if (i < N_O) {
        float4 v = ((const float4*)Wo)[i];
        __half2 a = __floats2half2_rn(v.x * 64.f, v.y * 64.f);
        __half2 b = __floats2half2_rn(v.z * 64.f, v.w * 64.f);
        uint2 o;
        o.x = *reinterpret_cast<uint32_t*>(&a);
        o.y = *reinterpret_cast<uint32_t*>(&b);
        ((uint2*)g_Wo)[i] = o;
        return;
    }
    i -= N_O;
    if (i < N_R) {
        int t = i >> 5;
        int c = i & 31;
        double inv = pow(10000.0, -(double)c / 32.0);
        double a   = (double)t * inv;
        g_cos[i] = (float)cos(a);
        g_sin[i] = (float)sin(a);
    }
}

// ---------------------------------------------------------------------------
// Fused QKV int8 2-digit GEMM + RoPE epilogue.
// 512 threads (16 warps: 8 row-groups x 2 col-groups), BK=64, 3-stage,
// single barrier per chunk.
// ---------------------------------------------------------------------------
#define PI8  80                 /* bytes per 64B row + 16 pad */
#define MAT8 (128 * PI8)        /* 10240 B */
#define STG8 (4 * MAT8)         /* 40960 B */
#define GEMM8_SMEM (3 * STG8)   /* 122880 B */

__global__ void __launch_bounds__(512, 1)
gemm8_qkv(const int8_t* __restrict__ Ah, const int8_t* __restrict__ Al,
          const int8_t* __restrict__ Wh, const int8_t* __restrict__ Wl)
{
    extern __shared__ char smc[];
    const uint32_t sb = smem_u32(smc);
    const int tid  = threadIdx.x;
    const int lane = tid & 31;
    const int wid  = tid >> 5;
    const int wm = (wid & 7) * 16;     // 8 row groups
    const int wn = (wid >> 3) * 64;    // 2 col groups
    const int m0 = blockIdx.y * 128;
    const int n0 = blockIdx.x * 128;
    const int K  = DM;

    int hh[8][4], mid[8][4];
#pragma unroll
    for (int nt = 0; nt < 8; nt++)
#pragma unroll
        for (int j = 0; j < 4; j++) { hh[nt][j] = 0; mid[nt][j] = 0; }

    const int quad  = lane >> 3;
    const int arow  = (lane & 7) + (quad & 1) * 8;
    const int acolB = (quad >> 1) * 16;
    const int brow  = (lane & 7) + (quad >> 1) * 8;
    const int bcolB = (quad & 1) * 16;

    const int row = tid >> 2;      // 0..127
    const int cc  = tid & 3;       // 16B quarter of the 64B row
    const int nch = K / 64;        /* 32 */

#define L8(c, sel) do {                                                       \
    uint32_t d0 = sb + (sel) * STG8 + (uint32_t)(row * PI8 + cc * 16);        \
    size_t ao = (size_t)(m0 + row) * K + (size_t)(c) * 64 + cc * 16;          \
    size_t wo = (size_t)(n0 + row) * K + (size_t)(c) * 64 + cc * 16;          \
    CP16(d0,            Ah + ao);                                             \
    CP16(d0 + MAT8,     Al + ao);                                             \
    CP16(d0 + 2 * MAT8, Wh + wo);                                             \
    CP16(d0 + 3 * MAT8, Wl + wo);                                             \
    CPCOMMIT();                                                               \
} while (0)

    L8(0, 0);
    L8(1, 1);

    for (int c = 0; c < nch; c++) {
        if (c + 1 < nch) { CPWAIT(1); } else { CPWAIT(0); }
        __syncthreads();
        if (c + 2 < nch) L8(c + 2, (c + 2) % 3);

        const uint32_t base = sb + (c % 3) * STG8;

#pragma unroll
        for (int ks = 0; ks < 64; ks += 32) {
            uint32_t ahi[4], alo[4];
            {
                uint32_t addr = base + (uint32_t)((wm + arow) * PI8 + ks + acolB);
                ldmx4(ahi[0], ahi[1], ahi[2], ahi[3], addr);
                ldmx4(alo[0], alo[1], alo[2], alo[3], addr + MAT8);
            }
#pragma unroll
            for (int np = 0; np < 4; np++) {
                uint32_t baddr = base + 2 * MAT8 +
                    (uint32_t)((wn + np * 16 + brow) * PI8 + ks + bcolB);
                uint32_t bh[4], bl[4];
                ldmx4(bh[0], bh[1], bh[2], bh[3], baddr);
                ldmx4(bl[0], bl[1], bl[2], bl[3], baddr + MAT8);
                uint32_t b0h[2] = {bh[0], bh[1]}, b1h[2] = {bh[2], bh[3]};
                uint32_t b0l[2] = {bl[0], bl[1]}, b1l[2] = {bl[2], bl[3]};
                mma_s8(hh[2 * np],      ahi, b0h);
                mma_s8(hh[2 * np + 1],  ahi, b1h);
                mma_s8(mid[2 * np],     ahi, b0l);
                mma_s8(mid[2 * np + 1], ahi, b1l);
                mma_s8(mid[2 * np],     alo, b0h);
                mma_s8(mid[2 * np + 1], alo, b1h);
            }
        }
    }
#undef L8

    // ------------- epilogue (region-uniform per CTA) -------------
    const int r0 = m0 + wm + (lane >> 2);
    if (n0 < DM + KVD) {
        const bool isQ = (n0 < DM);
        const float osc = isQ ? 0.125f : 1.f;
        half* dst = isQ ? g_Qh : g_Kh;
        const int dstride = isQ ? DM : KVD;
        const int coff = isQ ? 0 : DM;
#pragma unroll
        for (int nt = 0; nt < 4; nt++) {
            const int colb = n0 + wn + nt * 8 + (lane & 3) * 2;
            const int i = colb & 31;
            float o0[4], o1[4];
#pragma unroll
            for (int j = 0; j < 4; j++) {
                int rr = r0 + ((j >> 1) << 3);
                int t  = rr & (TT - 1);
                int ii = i + (j & 1);
                float cv = g_cos[t * 32 + ii];
                float sv = g_sin[t * 32 + ii];
                float v0 = comb8(hh[nt][j],     mid[nt][j]);
                float v1 = comb8(hh[nt + 4][j], mid[nt + 4][j]);
                o0[j] = (v0 * cv - v1 * sv) * osc;
                o1[j] = (v1 * cv + v0 * sv) * osc;
            }
            size_t b0 = (size_t)r0 * dstride + (colb - coff);
            size_t b1 = (size_t)(r0 + 8) * dstride + (colb - coff);
            *(uint32_t*)(dst + b0)      = packh(o0[0], o0[1]);
            *(uint32_t*)(dst + b0 + 32) = packh(o1[0], o1[1]);
            *(uint32_t*)(dst + b1)      = packh(o0[2], o0[3]);
            *(uint32_t*)(dst + b1 + 32) = packh(o1[2], o1[3]);
        }
    } else {
#pragma unroll
        for (int nt = 0; nt < 8; nt++) {
            int col = n0 - (DM + KVD) + wn + nt * 8 + (lane & 3) * 2;
#pragma unroll
            for (int j = 0; j < 4; j++) {
                int r = r0 + ((j >> 1) << 3);
                int cc2 = col + (j & 1);
                int b = r >> 11, t = r & (TT - 1);
                size_t di = (((size_t)b * NKV + (cc2 >> 6)) * DH + (cc2 & 63)) * TT + t;
                g_Vth[di] = __float2half_rn(comb8(hh[nt][j], mid[nt][j]));
            }
        }
    }
}

// ---------------------------------------------------------------------------
// fp16 1-term GEMM (output projection): 512 threads, BK=64, 3-stage,
// single barrier per chunk.
// ---------------------------------------------------------------------------
#define PITCH2 72                    /* halves: 64 data + 8 pad */
#define MAT2  (128 * PITCH2 * 2)     /* 18432 B */
#define STAGE2 (2 * MAT2)            /* 36864 B */
#define GEMM2_SMEM (3 * STAGE2)      /* 110592 B */
#define OUT_SCALE (1.f / 1024.f)

__global__ void __launch_bounds__(512, 1)
gemm2_f32(const half* __restrict__ Ah, const half* __restrict__ Wh,
          float* __restrict__ C, int N, int K)
{
    extern __shared__ char smc[];
    const uint32_t sb = smem_u32(smc);
    const int tid  = threadIdx.x;
    const int lane = tid & 31;
    const int wid  = tid >> 5;
    const int wm = (wid & 7) * 16;
    const int wn = (wid >> 3) * 64;
    const int m0 = blockIdx.y * 128;
    const int n0 = blockIdx.x * 128;

    float acc[8][4];
#pragma unroll
    for (int nt = 0; nt < 8; nt++)
#pragma unroll
        for (int j = 0; j < 4; j++) acc[nt][j] = 0.f;

    const int quad = lane >> 3;
    const int arow_off = (lane & 7) + (quad & 1) * 8;
    const int acol_off = (quad >> 1) * 8;
    const int brow_off = (lane & 7) + (quad >> 1) * 8;
    const int bcol_off = (quad & 1) * 8;

    const int nch = K / 64;        /* 32 */
    const int r_  = tid >> 3;      /* 0..63, l adds 64 */
    const int q_  = tid & 7;       /* 16B eighth of 128B row */

#define LOAD2(c, sel) do {                                                    \
    _Pragma("unroll")                                                         \
    for (int l = 0; l < 2; l++) {                                             \
        int row = r_ + l * 64;                                                \
        uint32_t d0 = sb + (sel) * STAGE2 +                                   \
                      (uint32_t)(row * PITCH2 + q_ * 8) * 2;                  \
        size_t aoff = (size_t)(m0 + row) * K + (c) * 64 + q_ * 8;             \
        size_t woff = (size_t)(n0 + row) * K + (c) * 64 + q_ * 8;             \
        CP16(d0,        Ah + aoff);                                           \
        CP16(d0 + MAT2, Wh + woff);                                           \
    }                                                                         \
    CPCOMMIT();                                                               \
} while (0)

    LOAD2(0, 0);
    LOAD2(1, 1);

    for (int c = 0; c < nch; c++) {
        if (c + 1 < nch) { CPWAIT(1); } else { CPWAIT(0); }
        __syncthreads();
        if (c + 2 < nch) LOAD2(c + 2, (c + 2) % 3);

        const uint32_t base = sb + (c % 3) * STAGE2;
#pragma unroll
        for (int ks = 0; ks < 64; ks += 16) {
            uint32_t ah[4];
            {
                uint32_t addr = base +
                    ((uint32_t)((wm + arow_off) * PITCH2 + ks + acol_off) << 1);
                ldmx4(ah[0], ah[1], ah[2], ah[3], addr);
            }
            uint32_t bh[8][2];
#pragma unroll
            for (int np = 0; np < 4; np++) {
                uint32_t addr = base + MAT2 +
                    ((uint32_t)((wn + np * 16 + brow_off) * PITCH2 + ks + bcol_off) << 1);
                uint32_t r0, r1, r2, r3;
                ldmx4(r0, r1, r2, r3, addr);
                bh[2 * np][0] = r0; bh[2 * np][1] = r1;
                bh[2 * np + 1][0] = r2; bh[2 * np + 1][1] = r3;
            }
#pragma unroll
            for (int nt = 0; nt < 8; nt++)
                mma16816(acc[nt], ah, bh[nt]);
        }
    }
#undef LOAD2

    const int row = m0 + wm + (lane >> 2);
#pragma unroll
    for (int nt = 0; nt < 8; nt++) {
        int col = n0 + wn + nt * 8 + (lane & 3) * 2;
        *(float2*)(C + (size_t)row * N + col) =
            make_float2(acc[nt][0] * OUT_SCALE, acc[nt][1] * OUT_SCALE);
        *(float2*)(C + (size_t)(row + 8) * N + col) =
            make_float2(acc[nt][2] * OUT_SCALE, acc[nt][3] * OUT_SCALE);
    }
}

// ---------------------------------------------------------------------------
// Flash attention, single-term fp16, double-buffered cp.async,
// single barrier per key-block (round 13 version, unchanged).
// ---------------------------------------------------------------------------
#define KP 72
#define MATK (128 * KP * 2)          /* 18432 */
#define VP 136
#define VOFF (2 * MATK)              /* 36864 */
#define VMAT (64 * VP * 2)           /* 17408 */
#define ATTN_SMEM (VOFF + 2 * VMAT)  /* 71680 */

__global__ void __launch_bounds__(256, 1) attn_mma()
{
    extern __shared__ char smc[];
    const uint32_t sb = smem_u32(smc);

    const int tid  = threadIdx.x;
    const int lane = tid & 31;
    const int wid  = tid >> 5;
    const int wq   = wid * 16;

    const int quad = lane >> 3;
    const int arow_off = (lane & 7) + (quad & 1) * 8;
    const int acol_off = (quad >> 1) * 8;
    const int brow_off = (lane & 7) + (quad >> 1) * 8;
    const int bcol_off = (quad & 1) * 8;

    const int q0 = (gridDim.x - 1 - blockIdx.x) * 128;
    const int h  = blockIdx.y;
    const int b  = blockIdx.z;
    const int g  = h >> 2;

    const half* Kb  = g_Kh  + (size_t)b * TT * KVD + g * DH;
    const half* Vbh = g_Vth + ((size_t)b * NKV + g) * DH * TT;

#define ATT_LOAD(s0_, sel_) do {                                              \
    const uint32_t kb = sb + (sel_) * MATK;                                   \
    const uint32_t vb = sb + VOFF + (sel_) * VMAT;                            \
    _Pragma("unroll")                                                         \
    for (int l = 0; l < 4; l++) {                                             \
        int idx = tid + l * 256;                                              \
        int s  = idx >> 3, cq = idx & 7;                                      \
        CP16(kb + (uint32_t)(s * KP + cq * 8) * 2,                            \
             Kb + (size_t)((s0_) + s) * KVD + cq * 8);                        \
        int d  = idx >> 4, cv = idx & 15;                                     \
        CP16(vb + (uint32_t)(d * VP + cv * 8) * 2,                            \
             Vbh + (size_t)d * TT + (s0_) + cv * 8);                          \
    }                                                                         \
    CPCOMMIT();                                                               \
} while (0)

    {
        const half* Qph = g_Qh + ((size_t)b * TT + q0) * DM + h * DH;
#pragma unroll
        for (int l = 0; l < 4; l++) {
            int idx = tid + l * 256;
            int r   = idx >> 3;
            int cq  = idx & 7;
            uint32_t off = (uint32_t)(r * KP + cq * 8) * 2;
            *(uint4*)(smc + off) = *(const uint4*)(Qph + (size_t)r * DM + cq * 8);
        }
    }
    __syncthreads();

    uint32_t qh[4][4];
#pragma unroll
    for (int ks = 0; ks < 4; ks++) {
        uint32_t addr = sb + ((uint32_t)((wq + arow_off) * KP + ks * 16 + acol_off) << 1);
        ldmx4(qh[ks][0], qh[ks][1], qh[ks][2], qh[ks][3], addr);
    }
    __syncthreads();

    ATT_LOAD(0, 0);

    float oacc[8][4];
#pragma unroll
    for (int nt = 0; nt < 8; nt++)
#pragma unroll
        for (int j = 0; j < 4; j++) oacc[nt][j] = 0.f;
    float mrow0 = -1e30f, mrow1 = -1e30f, lrow0 = 0.f, lrow1 = 0.f;

    const int row0 = q0 + wq + (lane >> 2);
    const int row1 = row0 + 8;

    int it = 0;
    for (int s0 = 0; s0 <= q0; s0 += 128, it++) {
        const int sel = it & 1;
        CPWAIT(0);
        __syncthreads();
        if (s0 + 128 <= q0) ATT_LOAD(s0 + 128, sel ^ 1);

        const uint32_t kbuf = sb + sel * MATK;
        const uint32_t vbuf = sb + VOFF + sel * VMAT;

        float sacc[16][4];
#pragma unroll
        for (int nt = 0; nt < 16; nt++)
#pragma unroll
            for (int j = 0; j < 4; j++) sacc[nt][j] = 0.f;

#pragma unroll
        for (int np = 0; np < 8; np++) {
#pragma unroll
            for (int ks = 0; ks < 4; ks++) {
                uint32_t addr = kbuf +
                    ((uint32_t)((np * 16 + brow_off) * KP + ks * 16 + bcol_off) << 1);
                uint32_t h0, h1, h2, h3;
                ldmx4(h0, h1, h2, h3, addr);
                uint32_t bh0[2] = {h0, h1}, bh1[2] = {h2, h3};
                mma16816(sacc[2 * np],     qh[ks], bh0);
                mma16816(sacc[2 * np + 1], qh[ks], bh1);
            }
        }

        if (s0 == q0) {
            const int cbase = s0 + (lane & 3) * 2;
#pragma unroll
            for (int nt = 0; nt < 16; nt++) {
                int c0 = cbase + nt * 8;
                if (c0     > row0) sacc[nt][0] = -1e30f;
                if (c0 + 1 > row0) sacc[nt][1] = -1e30f;
                if (c0     > row1) sacc[nt][2] = -1e30f;
                if (c0 + 1 > row1) sacc[nt][3] = -1e30f;
            }
        }

        float mx0 = -1e30f, mx1 = -1e30f;
#pragma unroll
        for (int nt = 0; nt < 16; nt++) {
            mx0 = fmaxf(mx0, fmaxf(sacc[nt][0], sacc[nt][1]));
            mx1 = fmaxf(mx1, fmaxf(sacc[nt][2], sacc[nt][3]));
        }
        mx0 = fmaxf(mx0, __shfl_xor_sync(0xffffffffu, mx0, 1));
        mx0 = fmaxf(mx0, __shfl_xor_sync(0xffffffffu, mx0, 2));
        mx1 = fmaxf(mx1, __shfl_xor_sync(0xffffffffu, mx1, 1));
        mx1 = fmaxf(mx1, __shfl_xor_sync(0xffffffffu, mx1, 2));

        float mnew0 = fmaxf(mrow0, mx0);
        float mnew1 = fmaxf(mrow1, mx1);
        float alpha0 = __expf(mrow0 - mnew0);
        float alpha1 = __expf(mrow1 - mnew1);

        uint32_t ph[8][4];
        float rs0 = 0.f, rs1 = 0.f;
#pragma unroll
        for (int ks = 0; ks < 8; ks++) {
#pragma unroll
            for (int half_ = 0; half_ < 2; half_++) {
                int nt = 2 * ks + half_;
                float p0 = __expf(sacc[nt][0] - mnew0);
                float p1 = __expf(sacc[nt][1] - mnew0);
                float p2 = __expf(sacc[nt][2] - mnew1);
                float p3 = __expf(sacc[nt][3] - mnew1);
                rs0 += p0 + p1;
                rs1 += p2 + p3;
                ph[ks][2 * half_]     = packh(p0, p1);
                ph[ks][2 * half_ + 1] = packh(p2, p3);
            }
        }
        rs0 += __shfl_xor_sync(0xffffffffu, rs0, 1);
        rs0 += __shfl_xor_sync(0xffffffffu, rs0, 2);
        rs1 += __shfl_xor_sync(0xffffffffu, rs1, 1);
        rs1 += __shfl_xor_sync(0xffffffffu, rs1, 2);

        lrow0 = lrow0 * alpha0 + rs0;
        lrow1 = lrow1 * alpha1 + rs1;
        mrow0 = mnew0;
        mrow1 = mnew1;
#pragma unroll
        for (int nt = 0; nt < 8; nt++) {
            oacc[nt][0] *= alpha0;
            oacc[nt][1] *= alpha0;
            oacc[nt][2] *= alpha1;
            oacc[nt][3] *= alpha1;
        }

#pragma unroll
        for (int np = 0; np < 4; np++) {
#pragma unroll
            for (int ks = 0; ks < 8; ks++) {
                uint32_t addr = vbuf +
                    ((uint32_t)((np * 16 + brow_off) * VP + ks * 16 + bcol_off) << 1);
                uint32_t h0, h1, h2, h3;
                ldmx4(h0, h1, h2, h3, addr);
                uint32_t bh0[2] = {h0, h1}, bh1[2] = {h2, h3};
                mma16816(oacc[2 * np],     ph[ks], bh0);
                mma16816(oacc[2 * np + 1], ph[ks], bh1);
            }
        }
    }
#undef ATT_LOAD

    float inv0 = 16.f / lrow0;
    float inv1 = 16.f / lrow1;
    const size_t o0 = ((size_t)b * TT + row0) * DM + h * DH + (lane & 3) * 2;
    const size_t o1 = ((size_t)b * TT + row1) * DM + h * DH + (lane & 3) * 2;
#pragma unroll
    for (int nt = 0; nt < 8; nt++) {
        *(uint32_t*)(g_Ah + o0 + nt * 8) =
            packh(oacc[nt][0] * inv0, oacc[nt][1] * inv0);
        *(uint32_t*)(g_Ah + o1 + nt * 8) =
            packh(oacc[nt][2] * inv1, oacc[nt][3] * inv1);
    }
}

// ---------------------------------------------------------------------------
extern "C" void kernel_launch(void* const* d_in, const int* in_sizes, int n_in,
                              void* d_out, int out_size)
{
    const float* x  = (const float*)d_in[0];
    const float* Wq = (const float*)d_in[1];
    const float* Wk = (const float*)d_in[2];
    const float* Wv = (const float*)d_in[3];
    const float* Wo = (const float*)d_in[4];
    float* out = (float*)d_out;

    int8_t *x8h, *x8l, *wc8h, *wc8l;
    half *wo, *ah;
    cudaGetSymbolAddress((void**)&x8h, g_x8h);   cudaGetSymbolAddress((void**)&x8l, g_x8l);
    cudaGetSymbolAddress((void**)&wc8h, g_Wc8h); cudaGetSymbolAddress((void**)&wc8l, g_Wc8l);
    cudaGetSymbolAddress((void**)&wo, g_Wo);
    cudaGetSymbolAddress((void**)&ah, g_Ah);

    cudaFuncSetAttribute(gemm8_qkv, cudaFuncAttributeMaxDynamicSharedMemorySize,
                         GEMM8_SMEM);
    cudaFuncSetAttribute(gemm2_f32, cudaFuncAttributeMaxDynamicSharedMemorySize,
                         GEMM2_SMEM);
    cudaFuncSetAttribute(attn_mma, cudaFuncAttributeMaxDynamicSharedMemorySize,
                         ATTN_SMEM);

    // ---- fused precompute (one launch)
    prep_kernel<<<(N_PREP + 255) / 256, 256>>>(x, Wq, Wk, Wv, Wo);

    // ---- fused QKV projection + RoPE (IMMA, 512 threads)
    gemm8_qkv<<<dim3(NC / 128, BT / 128), 512, GEMM8_SMEM>>>(x8h, x8l, wc8h, wc8l);

    // ---- attention (pipelined single-term fp16 HMMA)
    attn_mma<<<dim3(TT / 128, NH, BB), 256, ATTN_SMEM>>>();

    // ---- output projection (single-term fp16, 512 threads)
    gemm2_f32<<<dim3(DM / 128, BT / 128), 512, GEMM2_SMEM>>>(ah, wo, out, DM, DM);
}

// round 16
// speedup vs baseline: 1.1337x; 1.1337x over previous
#include <cuda_runtime.h>
#include <cuda_fp16.h>
#include <math.h>
#include <stdint.h>

#define BB  2
#define TT  2048
#define DM  2048
#define NH  32
#define NKV 8
#define DH  64
#define BT  (BB*TT)
#define KVD (NKV*DH)   /* 512 */
#define NC  (DM + 2*KVD)   /* 3072 combined output cols */

#define S_X    4096.f          /* 2^12 */
#define S_W    262144.f        /* 2^18 */
#define INV_SC (1.f / 1073741824.f)   /* 2^-30 */

// ---------------- scratch (device globals; no allocations allowed) ----------
__device__ int8_t g_x8h[(size_t)BT * DM],  g_x8l[(size_t)BT * DM];
__device__ int8_t g_Wc8h[(size_t)NC * DM], g_Wc8l[(size_t)NC * DM]; // Wq|Wk|Wv

__device__ half g_Wo[(size_t)DM * DM];                            // Wo * 64 single
__device__ half g_Ah[(size_t)BT * DM];                            // attn out x16 single

__device__ half g_Qh[(size_t)BT * DM];                            // roped, x0.125 single
__device__ half g_Kh[(size_t)BT * KVD];                           // roped, single
__device__ half g_Vth[(size_t)BT * KVD];                          // (b,g,d,t) single

__device__ float g_cos[TT * 32];
__device__ float g_sin[TT * 32];

// ===================== helpers ======================
__device__ __forceinline__ uint32_t smem_u32(const void* p) {
    uint32_t a;
    asm("{ .reg .u64 t; cvta.to.shared.u64 t, %1; cvt.u32.u64 %0, t; }"
        : "=r"(a) : "l"(p));
    return a;
}

#define CP16(dst, src) \
    asm volatile("cp.async.cg.shared.global [%0], [%1], 16;" \
                 :: "r"(dst), "l"(src) : "memory")
#define CPCOMMIT() asm volatile("cp.async.commit_group;" ::: "memory")
#define CPWAIT(n)  asm volatile("cp.async.wait_group %0;" :: "n"(n) : "memory")

__device__ __forceinline__ void ldmx4(uint32_t& r0, uint32_t& r1,
                                      uint32_t& r2, uint32_t& r3, uint32_t a) {
    asm volatile("ldmatrix.sync.aligned.m8n8.x4.shared.b16 {%0,%1,%2,%3}, [%4];"
                 : "=r"(r0), "=r"(r1), "=r"(r2), "=r"(r3) : "r"(a));
}

__device__ __forceinline__ void mma16816(float* d, const uint32_t* a,
                                         const uint32_t* b) {
    asm volatile(
        "mma.sync.aligned.m16n8k16.row.col.f32.f16.f16.f32 "
        "{%0,%1,%2,%3},{%4,%5,%6,%7},{%8,%9},{%0,%1,%2,%3};"
        : "+f"(d[0]), "+f"(d[1]), "+f"(d[2]), "+f"(d[3])
        : "r"(a[0]), "r"(a[1]), "r"(a[2]), "r"(a[3]), "r"(b[0]), "r"(b[1]));
}

__device__ __forceinline__ void mma_s8(int* d, const uint32_t* a,
                                       const uint32_t* b) {
    asm volatile(
        "mma.sync.aligned.m16n8k32.row.col.s32.s8.s8.s32 "
        "{%0,%1,%2,%3},{%4,%5,%6,%7},{%8,%9},{%0,%1,%2,%3};"
        : "+r"(d[0]), "+r"(d[1]), "+r"(d[2]), "+r"(d[3])
        : "r"(a[0]), "r"(a[1]), "r"(a[2]), "r"(a[3]), "r"(b[0]), "r"(b[1]));
}

__device__ __forceinline__ uint32_t packh(float a, float b) {
    __half2 t = __floats2half2_rn(a, b);
    return *reinterpret_cast<uint32_t*>(&t);
}

// 16-bit fixed point -> two int8 digits (hi*256 + lo == q, exact)
__device__ __forceinline__ void qsplit(float v, float S, int8_t& hi, int8_t& lo) {
    int q = __float2int_rn(v * S);
    q = max(-32512, min(32512, q));
    int l = ((q + 128) & 255) - 128;
    hi = (int8_t)((q - l) >> 8);
    lo = (int8_t)l;
}

__device__ __forceinline__ float comb8(int hh, int mid) {
    return fmaf((float)hh, 65536.f, (float)mid * 256.f) * INV_SC;
}

// ---------------------------------------------------------------------------
// fused precompute: quant x | quant Wq/Wk/Wv | conv Wo | rope table
// ---------------------------------------------------------------------------
#define N_X (BT * DM / 4)
#define N_W (NC * DM / 4)
#define N_O (DM * DM / 4)
#define N_R (TT * 32)
#define N_PREP (N_X + N_W + N_O + N_R)

__global__ void prep_kernel(const float* __restrict__ x,
                            const float* __restrict__ Wq,
                            const float* __restrict__ Wk,
                            const float* __restrict__ Wv,
                            const float* __restrict__ Wo)
{
    int i = blockIdx.x * blockDim.x + threadIdx.x;
    if (i < N_X) {
        float4 v = ((const float4*)x)[i];
        int8_t h0, h1, h2, h3, l0, l1, l2, l3;
        qsplit(v.x, S_X, h0, l0);
        qsplit(v.y, S_X, h1, l1);
        qsplit(v.z, S_X, h2, l2);
        qsplit(v.w, S_X, h3, l3);
        ((char4*)g_x8h)[i] = make_char4(h0, h1, h2, h3);
        ((char4*)g_x8l)[i] = make_char4(l0, l1, l2, l3);
        return;
    }
    i -= N_X;
    if (i < N_W) {
        const int nq = DM * DM / 4;
        const int nk = KVD * DM / 4;
        const float* src;
        int si;
        if (i < nq)           { src = Wq; si = i; }
        else if (i < nq + nk) { src = Wk; si = i - nq; }
        else                  { src = Wv; si = i - nq - nk; }
        float4 v = ((const float4*)src)[si];
        int8_t h0, h1, h2, h3, l0, l1, l2, l3;
        qsplit(v.x, S_W, h0, l0);
        qsplit(v.y, S_W, h1, l1);
        qsplit(v.z, S_W, h2, l2);
        qsplit(v.w, S_W, h3, l3);
        ((char4*)g_Wc8h)[i] = make_char4(h0, h1, h2, h3);
        ((char4*)g_Wc8l)[i] = make_char4(l0, l1, l2, l3);
        return;
    }
    i -= N_W;
    if (i < N_O) {
        float4 v = ((const float4*)Wo)[i];
        __half2 a = __floats2half2_rn(v.x * 64.f, v.y * 64.f);
        __half2 b = __floats2half2_rn(v.z * 64.f, v.w * 64.f);
        uint2 o;
        o.x = *reinterpret_cast<uint32_t*>(&a);
        o.y = *reinterpret_cast<uint32_t*>(&b);
        ((uint2*)g_Wo)[i] = o;
        return;
    }
    i -= N_O;
    if (i < N_R) {
        int t = i >> 5;
        int c = i & 31;
        double inv = pow(10000.0, -(double)c / 32.0);
        double a   = (double)t * inv;
        g_cos[i] = (float)cos(a);
        g_sin[i] = (float)sin(a);
    }
}

// ---------------------------------------------------------------------------
// Fused QKV int8 2-digit GEMM + RoPE epilogue.
// 256 threads, BK=64, 3-stage, single barrier per chunk (round 14 config).
// ---------------------------------------------------------------------------
#define PI8  80                 /* bytes per 64B row + 16 pad */
#define MAT8 (128 * PI8)        /* 10240 B */
#define STG8 (4 * MAT8)         /* 40960 B */
#define GEMM8_SMEM (3 * STG8)   /* 122880 B */

__global__ void __launch_bounds__(256, 1)
gemm8_qkv(const int8_t* __restrict__ Ah, const int8_t* __restrict__ Al,
          const int8_t* __restrict__ Wh, const int8_t* __restrict__ Wl)
{
    extern __shared__ char smc[];
    const uint32_t sb = smem_u32(smc);
    const int tid  = threadIdx.x;
    const int lane = tid & 31;
    const int wid  = tid >> 5;
    const int wm = (wid & 3) * 32;
    const int wn = (wid >> 2) * 64;
    const int m0 = blockIdx.y * 128;
    const int n0 = blockIdx.x * 128;
    const int K  = DM;

    int hh[2][8][4], mid[2][8][4];
#pragma unroll
    for (int mt = 0; mt < 2; mt++)
#pragma unroll
        for (int nt = 0; nt < 8; nt++)
#pragma unroll
            for (int j = 0; j < 4; j++) { hh[mt][nt][j] = 0; mid[mt][nt][j] = 0; }

    const int quad  = lane >> 3;
    const int arow  = (lane & 7) + (quad & 1) * 8;
    const int acolB = (quad >> 1) * 16;
    const int brow  = (lane & 7) + (quad >> 1) * 8;
    const int bcolB = (quad & 1) * 16;

    const int row = tid >> 2;      // 0..63 (l adds 64)
    const int cc  = tid & 3;       // 16B quarter of the 64B row
    const int nch = K / 64;        /* 32 */

#define L8(c, sel) do {                                                       \
    _Pragma("unroll")                                                         \
    for (int l = 0; l < 2; l++) {                                             \
        int r2 = row + l * 64;                                                \
        uint32_t d0 = sb + (sel) * STG8 + (uint32_t)(r2 * PI8 + cc * 16);     \
        size_t ao = (size_t)(m0 + r2) * K + (size_t)(c) * 64 + cc * 16;       \
        size_t wo = (size_t)(n0 + r2) * K + (size_t)(c) * 64 + cc * 16;       \
        CP16(d0,            Ah + ao);                                         \
        CP16(d0 + MAT8,     Al + ao);                                         \
        CP16(d0 + 2 * MAT8, Wh + wo);                                         \
        CP16(d0 + 3 * MAT8, Wl + wo);                                         \
    }                                                                         \
    CPCOMMIT();                                                               \
} while (0)

    L8(0, 0);
    L8(1, 1);

    for (int c = 0; c < nch; c++) {
        if (c + 1 < nch) { CPWAIT(1); } else { CPWAIT(0); }
        __syncthreads();
        if (c + 2 < nch) L8(c + 2, (c + 2) % 3);

        const uint32_t base = sb + (c % 3) * STG8;

#pragma unroll
        for (int ks = 0; ks < 64; ks += 32) {
            uint32_t ahi[2][4], alo[2][4];
#pragma unroll
            for (int mt = 0; mt < 2; mt++) {
                uint32_t addr = base +
                    (uint32_t)((wm + mt * 16 + arow) * PI8 + ks + acolB);
                ldmx4(ahi[mt][0], ahi[mt][1], ahi[mt][2], ahi[mt][3], addr);
                ldmx4(alo[mt][0], alo[mt][1], alo[mt][2], alo[mt][3], addr + MAT8);
            }
#pragma unroll
            for (int np = 0; np < 4; np++) {
                uint32_t baddr = base + 2 * MAT8 +
                    (uint32_t)((wn + np * 16 + brow) * PI8 + ks + bcolB);
                uint32_t bh[4], bl[4];
                ldmx4(bh[0], bh[1], bh[2], bh[3], baddr);
                ldmx4(bl[0], bl[1], bl[2], bl[3], baddr + MAT8);
                uint32_t b0h[2] = {bh[0], bh[1]}, b1h[2] = {bh[2], bh[3]};
                uint32_t b0l[2] = {bl[0], bl[1]}, b1l[2] = {bl[2], bl[3]};
#pragma unroll
                for (int mt = 0; mt < 2; mt++) {
                    mma_s8(hh[mt][2 * np],      ahi[mt], b0h);
                    mma_s8(hh[mt][2 * np + 1],  ahi[mt], b1h);
                    mma_s8(mid[mt][2 * np],     ahi[mt], b0l);
                    mma_s8(mid[mt][2 * np + 1], ahi[mt], b1l);
                    mma_s8(mid[mt][2 * np],     alo[mt], b0h);
                    mma_s8(mid[mt][2 * np + 1], alo[mt], b1h);
                }
            }
        }
    }
#undef L8

    // ------------- epilogue (region-uniform per CTA) -------------
    if (n0 < DM + KVD) {
        const bool isQ = (n0 < DM);
        const float osc = isQ ? 0.125f : 1.f;
        half* dst = isQ ? g_Qh : g_Kh;
        const int dstride = isQ ? DM : KVD;
        const int coff = isQ ? 0 : DM;
#pragma unroll
        for (int mt = 0; mt < 2; mt++) {
            const int r0 = m0 + wm + mt * 16 + (lane >> 2);
#pragma unroll
            for (int nt = 0; nt < 4; nt++) {
                const int colb = n0 + wn + nt * 8 + (lane & 3) * 2;
                const int i = colb & 31;
                float o0[4], o1[4];
#pragma unroll
                for (int j = 0; j < 4; j++) {
                    int rr = r0 + ((j >> 1) << 3);
                    int t  = rr & (TT - 1);
                    int ii = i + (j & 1);
                    float cv = g_cos[t * 32 + ii];
                    float sv = g_sin[t * 32 + ii];
                    float v0 = comb8(hh[mt][nt][j],     mid[mt][nt][j]);
                    float v1 = comb8(hh[mt][nt + 4][j], mid[mt][nt + 4][j]);
                    o0[j] = (v0 * cv - v1 * sv) * osc;
                    o1[j] = (v1 * cv + v0 * sv) * osc;
                }
                size_t b0 = (size_t)r0 * dstride + (colb - coff);
                size_t b1 = (size_t)(r0 + 8) * dstride + (colb - coff);
                *(uint32_t*)(dst + b0)      = packh(o0[0], o0[1]);
                *(uint32_t*)(dst + b0 + 32) = packh(o1[0], o1[1]);
                *(uint32_t*)(dst + b1)      = packh(o0[2], o0[3]);
                *(uint32_t*)(dst + b1 + 32) = packh(o1[2], o1[3]);
            }
        }
    } else {
#pragma unroll
        for (int mt = 0; mt < 2; mt++) {
            int rowt = m0 + wm + mt * 16 + (lane >> 2);
#pragma unroll
            for (int nt = 0; nt < 8; nt++) {
                int col = n0 - (DM + KVD) + wn + nt * 8 + (lane & 3) * 2;
#pragma unroll
                for (int j = 0; j < 4; j++) {
                    int r = rowt + ((j >> 1) << 3);
                    int cc2 = col + (j & 1);
                    int b = r >> 11, t = r & (TT - 1);
                    size_t di = (((size_t)b * NKV + (cc2 >> 6)) * DH + (cc2 & 63)) * TT + t;
                    g_Vth[di] = __float2half_rn(comb8(hh[mt][nt][j], mid[mt][nt][j]));
                }
            }
        }
    }
}

// ---------------------------------------------------------------------------
// fp16 1-term GEMM (output projection): BK=64, 2-stage, 2 CTAs/SM.
// wait(0) -> barrier -> issue-next pattern (prefetch distance = 1 chunk).
// ---------------------------------------------------------------------------
#define PITCH2 72                    /* halves: 64 data + 8 pad */
#define MAT2  (128 * PITCH2 * 2)     /* 18432 B */
#define STAGE2 (2 * MAT2)            /* 36864 B */
#define GEMM2_SMEM (2 * STAGE2)      /* 73728 B */
#define OUT_SCALE (1.f / 1024.f)

__global__ void __launch_bounds__(256, 2)
gemm2_f32(const half* __restrict__ Ah, const half* __restrict__ Wh,
          float* __restrict__ C, int N, int K)
{
    extern __shared__ char smc[];
    const uint32_t sb = smem_u32(smc);
    const int tid  = threadIdx.x;
    const int lane = tid & 31;
    const int wid  = tid >> 5;
    const int wm = (wid & 3) * 32;
    const int wn = (wid >> 2) * 64;
    const int m0 = blockIdx.y * 128;
    const int n0 = blockIdx.x * 128;

    float acc[2][8][4];
#pragma unroll
    for (int mt = 0; mt < 2; mt++)
#pragma unroll
        for (int nt = 0; nt < 8; nt++)
#pragma unroll
            for (int j = 0; j < 4; j++) acc[mt][nt][j] = 0.f;

    const int quad = lane >> 3;
    const int arow_off = (lane & 7) + (quad & 1) * 8;
    const int acol_off = (quad >> 1) * 8;
    const int brow_off = (lane & 7) + (quad >> 1) * 8;
    const int bcol_off = (quad & 1) * 8;

    const int nch = K / 64;        /* 32 */
    const int r_  = tid >> 3;      /* 0..31, l adds 32 */
    const int q_  = tid & 7;       /* 16B eighth of 128B row */

#define LOAD2(c, sel) do {                                                    \
    _Pragma("unroll")                                                         \
    for (int l = 0; l < 4; l++) {                                             \
        int row = r_ + l * 32;                                                \
        uint32_t d0 = sb + (sel) * STAGE2 +                                   \
                      (uint32_t)(row * PITCH2 + q_ * 8) * 2;                  \
        size_t aoff = (size_t)(m0 + row) * K + (c) * 64 + q_ * 8;             \
        size_t woff = (size_t)(n0 + row) * K + (c) * 64 + q_ * 8;             \
        CP16(d0,        Ah + aoff);                                           \
        CP16(d0 + MAT2, Wh + woff);                                           \
    }                                                                         \
    CPCOMMIT();                                                               \
} while (0)

    LOAD2(0, 0);

    for (int c = 0; c < nch; c++) {
        CPWAIT(0);
        __syncthreads();
        // next chunk's load goes to buffer (c+1)&1 = (c-1)&1, whose last
        // readers (compute c-1) all passed this barrier.
        if (c + 1 < nch) LOAD2(c + 1, (c + 1) & 1);

        const uint32_t base = sb + (c & 1) * STAGE2;
#pragma unroll
        for (int ks = 0; ks < 64; ks += 16) {
            uint32_t ah[2][4];
#pragma unroll
            for (int mt = 0; mt < 2; mt++) {
                uint32_t addr = base +
                    ((uint32_t)((wm + mt * 16 + arow_off) * PITCH2 + ks + acol_off) << 1);
                ldmx4(ah[mt][0], ah[mt][1], ah[mt][2], ah[mt][3], addr);
            }
            uint32_t bh[8][2];
#pragma unroll
            for (int np = 0; np < 4; np++) {
                uint32_t addr = base + MAT2 +
                    ((uint32_t)((wn + np * 16 + brow_off) * PITCH2 + ks + bcol_off) << 1);
                uint32_t r0, r1, r2, r3;
                ldmx4(r0, r1, r2, r3, addr);
                bh[2 * np][0] = r0; bh[2 * np][1] = r1;
                bh[2 * np + 1][0] = r2; bh[2 * np + 1][1] = r3;
            }
#pragma unroll
            for (int mt = 0; mt < 2; mt++)
#pragma unroll
                for (int nt = 0; nt < 8; nt++)
                    mma16816(acc[mt][nt], ah[mt], bh[nt]);
        }
    }
#undef LOAD2

#pragma unroll
    for (int mt = 0; mt < 2; mt++) {
        int row = m0 + wm + mt * 16 + (lane >> 2);
#pragma unroll
        for (int nt = 0; nt < 8; nt++) {
            int col = n0 + wn + nt * 8 + (lane & 3) * 2;
            *(float2*)(C + (size_t)row * N + col) =
                make_float2(acc[mt][nt][0] * OUT_SCALE, acc[mt][nt][1] * OUT_SCALE);
            *(float2*)(C + (size_t)(row + 8) * N + col) =
                make_float2(acc[mt][nt][2] * OUT_SCALE, acc[mt][nt][3] * OUT_SCALE);
        }
    }
}

// ---------------------------------------------------------------------------
// Flash attention, single-term fp16, double-buffered cp.async,
// single barrier per key-block (round 13/14 version, unchanged).
// ---------------------------------------------------------------------------
#define KP 72
#define MATK (128 * KP * 2)          /* 18432 */
#define VP 136
#define VOFF (2 * MATK)              /* 36864 */
#define VMAT (64 * VP * 2)           /* 17408 */
#define ATTN_SMEM (VOFF + 2 * VMAT)  /* 71680 */

__global__ void __launch_bounds__(256, 1) attn_mma()
{
    extern __shared__ char smc[];
    const uint32_t sb = smem_u32(smc);

    const int tid  = threadIdx.x;
    const int lane = tid & 31;
    const int wid  = tid >> 5;
    const int wq   = wid * 16;

    const int quad = lane >> 3;
    const int arow_off = (lane & 7) + (quad & 1) * 8;
    const int acol_off = (quad >> 1) * 8;
    const int brow_off = (lane & 7) + (quad >> 1) * 8;
    const int bcol_off = (quad & 1) * 8;

    const int q0 = (gridDim.x - 1 - blockIdx.x) * 128;
    const int h  = blockIdx.y;
    const int b  = blockIdx.z;
    const int g  = h >> 2;

    const half* Kb  = g_Kh  + (size_t)b * TT * KVD + g * DH;
    const half* Vbh = g_Vth + ((size_t)b * NKV + g) * DH * TT;

#define ATT_LOAD(s0_, sel_) do {                                              \
    const uint32_t kb = sb + (sel_) * MATK;                                   \
    const uint32_t vb = sb + VOFF + (sel_) * VMAT;                            \
    _Pragma("unroll")                                                         \
    for (int l = 0; l < 4; l++) {                                             \
        int idx = tid + l * 256;                                              \
        int s  = idx >> 3, cq = idx & 7;                                      \
        CP16(kb + (uint32_t)(s * KP + cq * 8) * 2,                            \
             Kb + (size_t)((s0_) + s) * KVD + cq * 8);                        \
        int d  = idx >> 4, cv = idx & 15;                                     \
        CP16(vb + (uint32_t)(d * VP + cv * 8) * 2,                            \
             Vbh + (size_t)d * TT + (s0_) + cv * 8);                          \
    }                                                                         \
    CPCOMMIT();                                                               \
} while (0)

    {
        const half* Qph = g_Qh + ((size_t)b * TT + q0) * DM + h * DH;
#pragma unroll
        for (int l = 0; l < 4; l++) {
            int idx = tid + l * 256;
            int r   = idx >> 3;
            int cq  = idx & 7;
            uint32_t off = (uint32_t)(r * KP + cq * 8) * 2;
            *(uint4*)(smc + off) = *(const uint4*)(Qph + (size_t)r * DM + cq * 8);
        }
    }
    __syncthreads();

    uint32_t qh[4][4];
#pragma unroll
    for (int ks = 0; ks < 4; ks++) {
        uint32_t addr = sb + ((uint32_t)((wq + arow_off) * KP + ks * 16 + acol_off) << 1);
        ldmx4(qh[ks][0], qh[ks][1], qh[ks][2], qh[ks][3], addr);
    }
    __syncthreads();

    ATT_LOAD(0, 0);

    float oacc[8][4];
#pragma unroll
    for (int nt = 0; nt < 8; nt++)
#pragma unroll
        for (int j = 0; j < 4; j++) oacc[nt][j] = 0.f;
    float mrow0 = -1e30f, mrow1 = -1e30f, lrow0 = 0.f, lrow1 = 0.f;

    const int row0 = q0 + wq + (lane >> 2);
    const int row1 = row0 + 8;

    int it = 0;
    for (int s0 = 0; s0 <= q0; s0 += 128, it++) {
        const int sel = it & 1;
        CPWAIT(0);
        __syncthreads();
        if (s0 + 128 <= q0) ATT_LOAD(s0 + 128, sel ^ 1);

        const uint32_t kbuf = sb + sel * MATK;
        const uint32_t vbuf = sb + VOFF + sel * VMAT;

        float sacc[16][4];
#pragma unroll
        for (int nt = 0; nt < 16; nt++)
#pragma unroll
            for (int j = 0; j < 4; j++) sacc[nt][j] = 0.f;

#pragma unroll
        for (int np = 0; np < 8; np++) {
#pragma unroll
            for (int ks = 0; ks < 4; ks++) {
                uint32_t addr = kbuf +
                    ((uint32_t)((np * 16 + brow_off) * KP + ks * 16 + bcol_off) << 1);
                uint32_t h0, h1, h2, h3;
                ldmx4(h0, h1, h2, h3, addr);
                uint32_t bh0[2] = {h0, h1}, bh1[2] = {h2, h3};
                mma16816(sacc[2 * np],     qh[ks], bh0);
                mma16816(sacc[2 * np + 1], qh[ks], bh1);
            }
        }

        if (s0 == q0) {
            const int cbase = s0 + (lane & 3) * 2;
#pragma unroll
            for (int nt = 0; nt < 16; nt++) {
                int c0 = cbase + nt * 8;
                if (c0     > row0) sacc[nt][0] = -1e30f;
                if (c0 + 1 > row0) sacc[nt][1] = -1e30f;
                if (c0     > row1) sacc[nt][2] = -1e30f;
                if (c0 + 1 > row1) sacc[nt][3] = -1e30f;
            }
        }

        float mx0 = -1e30f, mx1 = -1e30f;
#pragma unroll
        for (int nt = 0; nt < 16; nt++) {
            mx0 = fmaxf(mx0, fmaxf(sacc[nt][0], sacc[nt][1]));
            mx1 = fmaxf(mx1, fmaxf(sacc[nt][2], sacc[nt][3]));
        }
        mx0 = fmaxf(mx0, __shfl_xor_sync(0xffffffffu, mx0, 1));
        mx0 = fmaxf(mx0, __shfl_xor_sync(0xffffffffu, mx0, 2));
        mx1 = fmaxf(mx1, __shfl_xor_sync(0xffffffffu, mx1, 1));
        mx1 = fmaxf(mx1, __shfl_xor_sync(0xffffffffu, mx1, 2));

        float mnew0 = fmaxf(mrow0, mx0);
        float mnew1 = fmaxf(mrow1, mx1);
        float alpha0 = __expf(mrow0 - mnew0);
        float alpha1 = __expf(mrow1 - mnew1);

        uint32_t ph[8][4];
        float rs0 = 0.f, rs1 = 0.f;
#pragma unroll
        for (int ks = 0; ks < 8; ks++) {
#pragma unroll
            for (int half_ = 0; half_ < 2; half_++) {
                int nt = 2 * ks + half_;
                float p0 = __expf(sacc[nt][0] - mnew0);
                float p1 = __expf(sacc[nt][1] - mnew0);
                float p2 = __expf(sacc[nt][2] - mnew1);
                float p3 = __expf(sacc[nt][3] - mnew1);
                rs0 += p0 + p1;
                rs1 += p2 + p3;
                ph[ks][2 * half_]     = packh(p0, p1);
                ph[ks][2 * half_ + 1] = packh(p2, p3);
            }
        }
        rs0 += __shfl_xor_sync(0xffffffffu, rs0, 1);
        rs0 += __shfl_xor_sync(0xffffffffu, rs0, 2);
        rs1 += __shfl_xor_sync(0xffffffffu, rs1, 1);
        rs1 += __shfl_xor_sync(0xffffffffu, rs1, 2);

        lrow0 = lrow0 * alpha0 + rs0;
        lrow1 = lrow1 * alpha1 + rs1;
        mrow0 = mnew0;
        mrow1 = mnew1;
#pragma unroll
        for (int nt = 0; nt < 8; nt++) {
            oacc[nt][0] *= alpha0;
            oacc[nt][1] *= alpha0;
            oacc[nt][2] *= alpha1;
            oacc[nt][3] *= alpha1;
        }

#pragma unroll
        for (int np = 0; np < 4; np++) {
#pragma unroll
            for (int ks = 0; ks < 8; ks++) {
                uint32_t addr = vbuf +
                    ((uint32_t)((np * 16 + brow_off) * VP + ks * 16 + bcol_off) << 1);
                uint32_t h0, h1, h2, h3;
                ldmx4(h0, h1, h2, h3, addr);
                uint32_t bh0[2] = {h0, h1}, bh1[2] = {h2, h3};
                mma16816(oacc[2 * np],     ph[ks], bh0);
                mma16816(oacc[2 * np + 1], ph[ks], bh1);
            }
        }
    }
#undef ATT_LOAD

    float inv0 = 16.f / lrow0;
    float inv1 = 16.f / lrow1;
    const size_t o0 = ((size_t)b * TT + row0) * DM + h * DH + (lane & 3) * 2;
    const size_t o1 = ((size_t)b * TT + row1) * DM + h * DH + (lane & 3) * 2;
#pragma unroll
    for (int nt = 0; nt < 8; nt++) {
        *(uint32_t*)(g_Ah + o0 + nt * 8) =
            packh(oacc[nt][0] * inv0, oacc[nt][1] * inv0);
        *(uint32_t*)(g_Ah + o1 + nt * 8) =
            packh(oacc[nt][2] * inv1, oacc[nt][3] * inv1);
    }
}

// ---------------------------------------------------------------------------
extern "C" void kernel_launch(void* const* d_in, const int* in_sizes, int n_in,
                              void* d_out, int out_size)
{
    const float* x  = (const float*)d_in[0];
    const float* Wq = (const float*)d_in[1];
    const float* Wk = (const float*)d_in[2];
    const float* Wv = (const float*)d_in[3];
    const float* Wo = (const float*)d_in[4];
    float* out = (float*)d_out;

    int8_t *x8h, *x8l, *wc8h, *wc8l;
    half *wo, *ah;
    cudaGetSymbolAddress((void**)&x8h, g_x8h);   cudaGetSymbolAddress((void**)&x8l, g_x8l);
    cudaGetSymbolAddress((void**)&wc8h, g_Wc8h); cudaGetSymbolAddress((void**)&wc8l, g_Wc8l);
    cudaGetSymbolAddress((void**)&wo, g_Wo);
    cudaGetSymbolAddress((void**)&ah, g_Ah);

    cudaFuncSetAttribute(gemm8_qkv, cudaFuncAttributeMaxDynamicSharedMemorySize,
                         GEMM8_SMEM);
    cudaFuncSetAttribute(gemm2_f32, cudaFuncAttributeMaxDynamicSharedMemorySize,
                         GEMM2_SMEM);
    cudaFuncSetAttribute(attn_mma, cudaFuncAttributeMaxDynamicSharedMemorySize,
                         ATTN_SMEM);

    // ---- fused precompute (one launch)
    prep_kernel<<<(N_PREP + 255) / 256, 256>>>(x, Wq, Wk, Wv, Wo);

    // ---- fused QKV projection + RoPE (IMMA, round-14 config)
    gemm8_qkv<<<dim3(NC / 128, BT / 128), 256, GEMM8_SMEM>>>(x8h, x8l, wc8h, wc8l);

    // ---- attention (pipelined single-term fp16 HMMA)
    attn_mma<<<dim3(TT / 128, NH, BB), 256, ATTN_SMEM>>>();

    // ---- output projection (single-term fp16, 2 CTAs/SM)
    gemm2_f32<<<dim3(DM / 128, BT / 128), 256, GEMM2_SMEM>>>(ah, wo, out, DM, DM);
}

// round 17
// speedup vs baseline: 1.2422x; 1.0957x over previous
#include <cuda_runtime.h>
#include <cuda_fp16.h>
#include <math.h>
#include <stdint.h>

#define BB  2
#define TT  2048
#define DM  2048
#define NH  32
#define NKV 8
#define DH  64
#define BT  (BB*TT)
#define KVD (NKV*DH)   /* 512 */
#define NC  (DM + 2*KVD)   /* 3072 combined output cols */

#define S_X    4096.f
#define S_W    262144.f
#define INV_SC (1.f / 1073741824.f)

// ---------------- scratch ----------
__device__ int8_t g_x8h[(size_t)BT * DM],  g_x8l[(size_t)BT * DM];
__device__ int8_t g_Wc8h[(size_t)NC * DM], g_Wc8l[(size_t)NC * DM];

__device__ half g_Wo[(size_t)DM * DM];
__device__ half g_Ah[(size_t)BT * DM];

__device__ half g_Qh[(size_t)BT * DM];
__device__ half g_Kh[(size_t)BT * KVD];
__device__ half g_Vth[(size_t)BT * KVD];

__device__ float g_cos[TT * 32];
__device__ float g_sin[TT * 32];

// ===================== helpers ======================
__device__ __forceinline__ uint32_t smem_u32(const void* p) {
    uint32_t a;
    asm("{ .reg .u64 t; cvta.to.shared.u64 t, %1; cvt.u32.u64 %0, t; }"
        : "=r"(a) : "l"(p));
    return a;
}

#define CP16(dst, src) \
    asm volatile("cp.async.cg.shared.global [%0], [%1], 16;" \
                 :: "r"(dst), "l"(src) : "memory")
#define CPCOMMIT() asm volatile("cp.async.commit_group;" ::: "memory")
#define CPWAIT(n)  asm volatile("cp.async.wait_group %0;" :: "n"(n) : "memory")

__device__ __forceinline__ void ldmx4(uint32_t& r0, uint32_t& r1,
                                      uint32_t& r2, uint32_t& r3, uint32_t a) {
    asm volatile("ldmatrix.sync.aligned.m8n8.x4.shared.b16 {%0,%1,%2,%3}, [%4];"
                 : "=r"(r0), "=r"(r1), "=r"(r2), "=r"(r3) : "r"(a));
}

__device__ __forceinline__ void mma16816(float* d, const uint32_t* a,
                                         const uint32_t* b) {
    asm volatile(
        "mma.sync.aligned.m16n8k16.row.col.f32.f16.f16.f32 "
        "{%0,%1,%2,%3},{%4,%5,%6,%7},{%8,%9},{%0,%1,%2,%3};"
        : "+f"(d[0]), "+f"(d[1]), "+f"(d[2]), "+f"(d[3])
        : "r"(a[0]), "r"(a[1]), "r"(a[2]), "r"(a[3]), "r"(b[0]), "r"(b[1]));
}

__device__ __forceinline__ void mma_s8(int* d, const uint32_t* a,
                                       const uint32_t* b) {
    asm volatile(
        "mma.sync.aligned.m16n8k32.row.col.s32.s8.s8.s32 "
        "{%0,%1,%2,%3},{%4,%5,%6,%7},{%8,%9},{%0,%1,%2,%3};"
        : "+r"(d[0]), "+r"(d[1]), "+r"(d[2]), "+r"(d[3])
        : "r"(a[0]), "r"(a[1]), "r"(a[2]), "r"(a[3]), "r"(b[0]), "r"(b[1]));
}

__device__ __forceinline__ uint32_t packh(float a, float b) {
    __half2 t = __floats2half2_rn(a, b);
    return *reinterpret_cast<uint32_t*>(&t);
}

__device__ __forceinline__ void qsplit(float v, float S, int8_t& hi, int8_t& lo) {
    int q = __float2int_rn(v * S);
    q = max(-32512, min(32512, q));
    int l = ((q + 128) & 255) - 128;
    hi = (int8_t)((q - l) >> 8);
    lo = (int8_t)l;
}

__device__ __forceinline__ float comb8(int hh, int mid) {
    return fmaf((float)hh, 65536.f, (float)mid * 256.f) * INV_SC;
}

// ---------------------------------------------------------------------------
// fused precompute
// ---------------------------------------------------------------------------
#define N_X (BT * DM / 4)
#define N_W (NC * DM / 4)
#define N_O (DM * DM / 4)
#define N_R (TT * 32)
#define N_PREP (N_X + N_W + N_O + N_R)

__global__ void prep_kernel(const float* __restrict__ x,
                            const float* __restrict__ Wq,
                            const float* __restrict__ Wk,
                            const float* __restrict__ Wv,
                            const float* __restrict__ Wo)
{
    int i = blockIdx.x * blockDim.x + threadIdx.x;
    if (i < N_X) {
        float4 v = ((const float4*)x)[i];
        int8_t h0, h1, h2, h3, l0, l1, l2, l3;
        qsplit(v.x, S_X, h0, l0);
        qsplit(v.y, S_X, h1, l1);
        qsplit(v.z, S_X, h2, l2);
        qsplit(v.w, S_X, h3, l3);
        ((char4*)g_x8h)[i] = make_char4(h0, h1, h2, h3);
        ((char4*)g_x8l)[i] = make_char4(l0, l1, l2, l3);
        return;
    }
    i -= N_X;
    if (i < N_W) {
        const int nq = DM * DM / 4;
        const int nk = KVD * DM / 4;
        const float* src;
        int si;
        if (i < nq)           { src = Wq; si = i; }
        else if (i < nq + nk) { src = Wk; si = i - nq; }
        else                  { src = Wv; si = i - nq - nk; }
        float4 v = ((const float4*)src)[si];
        int8_t h0, h1, h2, h3, l0, l1, l2, l3;
        qsplit(v.x, S_W, h0, l0);
        qsplit(v.y, S_W, h1, l1);
        qsplit(v.z, S_W, h2, l2);
        qsplit(v.w, S_W, h3, l3);
        ((char4*)g_Wc8h)[i] = make_char4(h0, h1, h2, h3);
        ((char4*)g_Wc8l)[i] = make_char4(l0, l1, l2, l3);
        return;
    }
    i -= N_W;
    if (i < N_O) {
        float4 v = ((const float4*)Wo)[i];
        __half2 a = __floats2half2_rn(v.x * 64.f, v.y * 64.f);
        __half2 b = __floats2half2_rn(v.z * 64.f, v.w * 64.f);
        uint2 o;
        o.x = *reinterpret_cast<uint32_t*>(&a);
        o.y = *reinterpret_cast<uint32_t*>(&b);
        ((uint2*)g_Wo)[i] = o;
        return;
    }
    i -= N_O;
    if (i < N_R) {
        int t = i >> 5;
        int c = i & 31;
        double inv = pow(10000.0, -(double)c / 32.0);
        double a   = (double)t * inv;
        g_cos[i] = (float)cos(a);
        g_sin[i] = (float)sin(a);
    }
}

// ---------------------------------------------------------------------------
// Fused QKV int8 2-digit GEMM + RoPE epilogue.
// 128x64 tile, 8 warps (32m x 32n each), BK=64, 2-stage, 2 CTAs/SM.
// Epilogue stages the fp32 tile through smem (pitch 65), then RoPE / V-store.
// ---------------------------------------------------------------------------
#define PI8   80                 /* bytes per 64B row + 16 pad */
#define MAT8A (128 * PI8)        /* 10240 B */
#define MAT8W (64 * PI8)         /* 5120 B */
#define STG8  (2 * MAT8A + 2 * MAT8W)  /* 30720 B */
#define GEMM8_SMEM (2 * STG8)    /* 61440 B */
#define EPI_P 65                 /* fp32 epilogue pitch (conflict-free) */

__global__ void __launch_bounds__(256, 2)
gemm8_qkv(const int8_t* __restrict__ Ah, const int8_t* __restrict__ Al,
          const int8_t* __restrict__ Wh, const int8_t* __restrict__ Wl)
{
    extern __shared__ char smc[];
    const uint32_t sb = smem_u32(smc);
    const int tid  = threadIdx.x;
    const int lane = tid & 31;
    const int wid  = tid >> 5;
    const int wm = (wid & 3) * 32;     // 4 row groups of 32
    const int wn = (wid >> 2) * 32;    // 2 col groups of 32
    const int m0 = blockIdx.y * 128;
    const int n0 = blockIdx.x * 64;
    const int K  = DM;

    int hh[2][4][4], mid[2][4][4];
#pragma unroll
    for (int mt = 0; mt < 2; mt++)
#pragma unroll
        for (int nt = 0; nt < 4; nt++)
#pragma unroll
            for (int j = 0; j < 4; j++) { hh[mt][nt][j] = 0; mid[mt][nt][j] = 0; }

    const int quad  = lane >> 3;
    const int arow  = (lane & 7) + (quad & 1) * 8;
    const int acolB = (quad >> 1) * 16;
    const int brow  = (lane & 7) + (quad >> 1) * 8;
    const int bcolB = (quad & 1) * 16;

    const int rowA = tid >> 2;     // 0..63 (l adds 64)
    const int cc   = tid & 3;      // 16B quarter of the 64B row
    const int nch  = K / 64;       /* 32 */

#define L8(c, sel) do {                                                       \
    const uint32_t s0_ = sb + (sel) * STG8;                                   \
    _Pragma("unroll")                                                         \
    for (int l = 0; l < 2; l++) {                                             \
        int r2 = rowA + l * 64;                                               \
        uint32_t d0 = s0_ + (uint32_t)(r2 * PI8 + cc * 16);                   \
        size_t ao = (size_t)(m0 + r2) * K + (size_t)(c) * 64 + cc * 16;       \
        CP16(d0,         Ah + ao);                                            \
        CP16(d0 + MAT8A, Al + ao);                                            \
    }                                                                         \
    {                                                                         \
        uint32_t d0 = s0_ + 2 * MAT8A + (uint32_t)(rowA * PI8 + cc * 16);     \
        size_t wo = (size_t)(n0 + rowA) * K + (size_t)(c) * 64 + cc * 16;     \
        CP16(d0,         Wh + wo);                                            \
        CP16(d0 + MAT8W, Wl + wo);                                            \
    }                                                                         \
    CPCOMMIT();                                                               \
} while (0)

    L8(0, 0);

    for (int c = 0; c < nch; c++) {
        CPWAIT(0);
        __syncthreads();
        if (c + 1 < nch) L8(c + 1, (c + 1) & 1);

        const uint32_t base = sb + (c & 1) * STG8;

#pragma unroll
        for (int ks = 0; ks < 64; ks += 32) {
            uint32_t ahi[2][4], alo[2][4];
#pragma unroll
            for (int mt = 0; mt < 2; mt++) {
                uint32_t addr = base +
                    (uint32_t)((wm + mt * 16 + arow) * PI8 + ks + acolB);
                ldmx4(ahi[mt][0], ahi[mt][1], ahi[mt][2], ahi[mt][3], addr);
                ldmx4(alo[mt][0], alo[mt][1], alo[mt][2], alo[mt][3], addr + MAT8A);
            }
#pragma unroll
            for (int np = 0; np < 2; np++) {
                uint32_t baddr = base + 2 * MAT8A +
                    (uint32_t)((wn + np * 16 + brow) * PI8 + ks + bcolB);
                uint32_t bh[4], bl[4];
                ldmx4(bh[0], bh[1], bh[2], bh[3], baddr);
                ldmx4(bl[0], bl[1], bl[2], bl[3], baddr + MAT8W);
                uint32_t b0h[2] = {bh[0], bh[1]}, b1h[2] = {bh[2], bh[3]};
                uint32_t b0l[2] = {bl[0], bl[1]}, b1l[2] = {bl[2], bl[3]};
#pragma unroll
                for (int mt = 0; mt < 2; mt++) {
                    mma_s8(hh[mt][2 * np],      ahi[mt], b0h);
                    mma_s8(hh[mt][2 * np + 1],  ahi[mt], b1h);
                    mma_s8(mid[mt][2 * np],     ahi[mt], b0l);
                    mma_s8(mid[mt][2 * np + 1], ahi[mt], b1l);
                    mma_s8(mid[mt][2 * np],     alo[mt], b0h);
                    mma_s8(mid[mt][2 * np + 1], alo[mt], b1h);
                }
            }
        }
    }
#undef L8

    // ------------- epilogue: stage fp32 tile in smem, then RoPE / V-store
    __syncthreads();   // done with stage buffers
    float* ep = (float*)smc;
#pragma unroll
    for (int mt = 0; mt < 2; mt++)
#pragma unroll
        for (int nt = 0; nt < 4; nt++)
#pragma unroll
            for (int j = 0; j < 4; j++) {
                int r = wm + mt * 16 + (lane >> 2) + ((j >> 1) << 3);
                int cidx = wn + nt * 8 + (lane & 3) * 2 + (j & 1);
                ep[r * EPI_P + cidx] = comb8(hh[mt][nt][j], mid[mt][nt][j]);
            }
    __syncthreads();

    if (n0 < DM + KVD) {
        const bool isQ = (n0 < DM);
        const float osc = isQ ? 0.125f : 1.f;
        half* dst = isQ ? g_Qh : g_Kh;
        const int dstride = isQ ? DM : KVD;
        const int coff = isQ ? 0 : DM;
        const int cbase = n0 - coff;
#pragma unroll
        for (int k = 0; k < 8; k++) {
            int idx = tid + k * 256;       // 0..2047
            int r = idx >> 4;              // 0..127
            int g = idx & 15;              // u32 group within 32-col half
            int i0 = 2 * g;
            float v00 = ep[r * EPI_P + i0];
            float v01 = ep[r * EPI_P + i0 + 1];
            float v10 = ep[r * EPI_P + i0 + 32];
            float v11 = ep[r * EPI_P + i0 + 33];
            int t = (m0 + r) & (TT - 1);
            float c0 = g_cos[t * 32 + i0], s0 = g_sin[t * 32 + i0];
            float c1 = g_cos[t * 32 + i0 + 1], s1 = g_sin[t * 32 + i0 + 1];
            float o00 = (v00 * c0 - v10 * s0) * osc;
            float o01 = (v01 * c1 - v11 * s1) * osc;
            float o10 = (v10 * c0 + v00 * s0) * osc;
            float o11 = (v11 * c1 + v01 * s1) * osc;
            size_t b0 = (size_t)(m0 + r) * dstride + cbase + i0;
            *(uint32_t*)(dst + b0)      = packh(o00, o01);
            *(uint32_t*)(dst + b0 + 32) = packh(o10, o11);
        }
    } else {
        const int hb = n0 - (DM + KVD);   // 64-aligned head base (0..511)
#pragma unroll
        for (int k = 0; k < 32; k++) {
            int idx = tid + k * 256;       // 0..8191
            int cloc = idx >> 7;           // 0..63 (dim within head)
            int r = idx & 127;             // token within tile
            float v = ep[r * EPI_P + cloc];
            int rt = m0 + r;
            int b = rt >> 11, t = rt & (TT - 1);
            int cc2 = hb + cloc;
            size_t di = (((size_t)b * NKV + (cc2 >> 6)) * DH + (cc2 & 63)) * TT + t;
            g_Vth[di] = __float2half_rn(v);
        }
    }
}

// ---------------------------------------------------------------------------
// fp16 1-term GEMM (output projection): BK=64, 2-stage, 2 CTAs/SM (round 16).
// ---------------------------------------------------------------------------
#define PITCH2 72
#define MAT2  (128 * PITCH2 * 2)
#define STAGE2 (2 * MAT2)
#define GEMM2_SMEM (2 * STAGE2)
#define OUT_SCALE (1.f / 1024.f)

__global__ void __launch_bounds__(256, 2)
gemm2_f32(const half* __restrict__ Ah, const half* __restrict__ Wh,
          float* __restrict__ C, int N, int K)
{
    extern __shared__ char smc[];
    const uint32_t sb = smem_u32(smc);
    const int tid  = threadIdx.x;
    const int lane = tid & 31;
    const int wid  = tid >> 5;
    const int wm = (wid & 3) * 32;
    const int wn = (wid >> 2) * 64;
    const int m0 = blockIdx.y * 128;
    const int n0 = blockIdx.x * 128;

    float acc[2][8][4];
#pragma unroll
    for (int mt = 0; mt < 2; mt++)
#pragma unroll
        for (int nt = 0; nt < 8; nt++)
#pragma unroll
            for (int j = 0; j < 4; j++) acc[mt][nt][j] = 0.f;

    const int quad = lane >> 3;
    const int arow_off = (lane & 7) + (quad & 1) * 8;
    const int acol_off = (quad >> 1) * 8;
    const int brow_off = (lane & 7) + (quad >> 1) * 8;
    const int bcol_off = (quad & 1) * 8;

    const int nch = K / 64;
    const int r_  = tid >> 3;
    const int q_  = tid & 7;

#define LOAD2(c, sel) do {                                                    \
    _Pragma("unroll")                                                         \
    for (int l = 0; l < 4; l++) {                                             \
        int row = r_ + l * 32;                                                \
        uint32_t d0 = sb + (sel) * STAGE2 +                                   \
                      (uint32_t)(row * PITCH2 + q_ * 8) * 2;                  \
        size_t aoff = (size_t)(m0 + row) * K + (c) * 64 + q_ * 8;             \
        size_t woff = (size_t)(n0 + row) * K + (c) * 64 + q_ * 8;             \
        CP16(d0,        Ah + aoff);                                           \
        CP16(d0 + MAT2, Wh + woff);                                           \
    }                                                                         \
    CPCOMMIT();                                                               \
} while (0)

    LOAD2(0, 0);

    for (int c = 0; c < nch; c++) {
        CPWAIT(0);
        __syncthreads();
        if (c + 1 < nch) LOAD2(c + 1, (c + 1) & 1);

        const uint32_t base = sb + (c & 1) * STAGE2;
#pragma unroll
        for (int ks = 0; ks < 64; ks += 16) {
            uint32_t ah[2][4];
#pragma unroll
            for (int mt = 0; mt < 2; mt++) {
                uint32_t addr = base +
                    ((uint32_t)((wm + mt * 16 + arow_off) * PITCH2 + ks + acol_off) << 1);
                ldmx4(ah[mt][0], ah[mt][1], ah[mt][2], ah[mt][3], addr);
            }
            uint32_t bh[8][2];
#pragma unroll
            for (int np = 0; np < 4; np++) {
                uint32_t addr = base + MAT2 +
                    ((uint32_t)((wn + np * 16 + brow_off) * PITCH2 + ks + bcol_off) << 1);
                uint32_t r0, r1, r2, r3;
                ldmx4(r0, r1, r2, r3, addr);
                bh[2 * np][0] = r0; bh[2 * np][1] = r1;
                bh[2 * np + 1][0] = r2; bh[2 * np + 1][1] = r3;
            }
#pragma unroll
            for (int mt = 0; mt < 2; mt++)
#pragma unroll
                for (int nt = 0; nt < 8; nt++)
                    mma16816(acc[mt][nt], ah[mt], bh[nt]);
        }
    }
#undef LOAD2

#pragma unroll
    for (int mt = 0; mt < 2; mt++) {
        int row = m0 + wm + mt * 16 + (lane >> 2);
#pragma unroll
        for (int nt = 0; nt < 8; nt++) {
            int col = n0 + wn + nt * 8 + (lane & 3) * 2;
            *(float2*)(C + (size_t)row * N + col) =
                make_float2(acc[mt][nt][0] * OUT_SCALE, acc[mt][nt][1] * OUT_SCALE);
            *(float2*)(C + (size_t)(row + 8) * N + col) =
                make_float2(acc[mt][nt][2] * OUT_SCALE, acc[mt][nt][3] * OUT_SCALE);
        }
    }
}

// ---------------------------------------------------------------------------
// Flash attention (round 13/14 version, unchanged).
// ---------------------------------------------------------------------------
#define KP 72
#define MATK (128 * KP * 2)
#define VP 136
#define VOFF (2 * MATK)
#define VMAT (64 * VP * 2)
#define ATTN_SMEM (VOFF + 2 * VMAT)

__global__ void __launch_bounds__(256, 1) attn_mma()
{
    extern __shared__ char smc[];
    const uint32_t sb = smem_u32(smc);

    const int tid  = threadIdx.x;
    const int lane = tid & 31;
    const int wid  = tid >> 5;
    const int wq   = wid * 16;

    const int quad = lane >> 3;
    const int arow_off = (lane & 7) + (quad & 1) * 8;
    const int acol_off = (quad >> 1) * 8;
    const int brow_off = (lane & 7) + (quad >> 1) * 8;
    const int bcol_off = (quad & 1) * 8;

    const int q0 = (gridDim.x - 1 - blockIdx.x) * 128;
    const int h  = blockIdx.y;
    const int b  = blockIdx.z;
    const int g  = h >> 2;

    const half* Kb  = g_Kh  + (size_t)b * TT * KVD + g * DH;
    const half* Vbh = g_Vth + ((size_t)b * NKV + g) * DH * TT;

#define ATT_LOAD(s0_, sel_) do {                                              \
    const uint32_t kb = sb + (sel_) * MATK;                                   \
    const uint32_t vb = sb + VOFF + (sel_) * VMAT;                            \
    _Pragma("unroll")                                                         \
    for (int l = 0; l < 4; l++) {                                             \
        int idx = tid + l * 256;                                              \
        int s  = idx >> 3, cq = idx & 7;                                      \
        CP16(kb + (uint32_t)(s * KP + cq * 8) * 2,                            \
             Kb + (size_t)((s0_) + s) * KVD + cq * 8);                        \
        int d  = idx >> 4, cv = idx & 15;                                     \
        CP16(vb + (uint32_t)(d * VP + cv * 8) * 2,                            \
             Vbh + (size_t)d * TT + (s0_) + cv * 8);                          \
    }                                                                         \
    CPCOMMIT();                                                               \
} while (0)

    {
        const half* Qph = g_Qh + ((size_t)b * TT + q0) * DM + h * DH;
#pragma unroll
        for (int l = 0; l < 4; l++) {
            int idx = tid + l * 256;
            int r   = idx >> 3;
            int cq  = idx & 7;
            uint32_t off = (uint32_t)(r * KP + cq * 8) * 2;
            *(uint4*)(smc + off) = *(const uint4*)(Qph + (size_t)r * DM + cq * 8);
        }
    }
    __syncthreads();

    uint32_t qh[4][4];
#pragma unroll
    for (int ks = 0; ks < 4; ks++) {
        uint32_t addr = sb + ((uint32_t)((wq + arow_off) * KP + ks * 16 + acol_off) << 1);
        ldmx4(qh[ks][0], qh[ks][1], qh[ks][2], qh[ks][3], addr);
    }
    __syncthreads();

    ATT_LOAD(0, 0);

    float oacc[8][4];
#pragma unroll
    for (int nt = 0; nt < 8; nt++)
#pragma unroll
        for (int j = 0; j < 4; j++) oacc[nt][j] = 0.f;
    float mrow0 = -1e30f, mrow1 = -1e30f, lrow0 = 0.f, lrow1 = 0.f;

    const int row0 = q0 + wq + (lane >> 2);
    const int row1 = row0 + 8;

    int it = 0;
    for (int s0 = 0; s0 <= q0; s0 += 128, it++) {
        const int sel = it & 1;
        CPWAIT(0);
        __syncthreads();
        if (s0 + 128 <= q0) ATT_LOAD(s0 + 128, sel ^ 1);

        const uint32_t kbuf = sb + sel * MATK;
        const uint32_t vbuf = sb + VOFF + sel * VMAT;

        float sacc[16][4];
#pragma unroll
        for (int nt = 0; nt < 16; nt++)
#pragma unroll
            for (int j = 0; j < 4; j++) sacc[nt][j] = 0.f;

#pragma unroll
        for (int np = 0; np < 8; np++) {
#pragma unroll
            for (int ks = 0; ks < 4; ks++) {
                uint32_t addr = kbuf +
                    ((uint32_t)((np * 16 + brow_off) * KP + ks * 16 + bcol_off) << 1);
                uint32_t h0, h1, h2, h3;
                ldmx4(h0, h1, h2, h3, addr);
                uint32_t bh0[2] = {h0, h1}, bh1[2] = {h2, h3};
                mma16816(sacc[2 * np],     qh[ks], bh0);
                mma16816(sacc[2 * np + 1], qh[ks], bh1);
            }
        }

        if (s0 == q0) {
            const int cbase = s0 + (lane & 3) * 2;
#pragma unroll
            for (int nt = 0; nt < 16; nt++) {
                int c0 = cbase + nt * 8;
                if (c0     > row0) sacc[nt][0] = -1e30f;
                if (c0 + 1 > row0) sacc[nt][1] = -1e30f;
                if (c0     > row1) sacc[nt][2] = -1e30f;
                if (c0 + 1 > row1) sacc[nt][3] = -1e30f;
            }
        }

        float mx0 = -1e30f, mx1 = -1e30f;
#pragma unroll
        for (int nt = 0; nt < 16; nt++) {
            mx0 = fmaxf(mx0, fmaxf(sacc[nt][0], sacc[nt][1]));
            mx1 = fmaxf(mx1, fmaxf(sacc[nt][2], sacc[nt][3]));
        }
        mx0 = fmaxf(mx0, __shfl_xor_sync(0xffffffffu, mx0, 1));
        mx0 = fmaxf(mx0, __shfl_xor_sync(0xffffffffu, mx0, 2));
        mx1 = fmaxf(mx1, __shfl_xor_sync(0xffffffffu, mx1, 1));
        mx1 = fmaxf(mx1, __shfl_xor_sync(0xffffffffu, mx1, 2));

        float mnew0 = fmaxf(mrow0, mx0);
        float mnew1 = fmaxf(mrow1, mx1);
        float alpha0 = __expf(mrow0 - mnew0);
        float alpha1 = __expf(mrow1 - mnew1);

        uint32_t ph[8][4];
        float rs0 = 0.f, rs1 = 0.f;
#pragma unroll
        for (int ks = 0; ks < 8; ks++) {
#pragma unroll
            for (int half_ = 0; half_ < 2; half_++) {
                int nt = 2 * ks + half_;
                float p0 = __expf(sacc[nt][0] - mnew0);
                float p1 = __expf(sacc[nt][1] - mnew0);
                float p2 = __expf(sacc[nt][2] - mnew1);
                float p3 = __expf(sacc[nt][3] - mnew1);
                rs0 += p0 + p1;
                rs1 += p2 + p3;
                ph[ks][2 * half_]     = packh(p0, p1);
                ph[ks][2 * half_ + 1] = packh(p2, p3);
            }
        }
        rs0 += __shfl_xor_sync(0xffffffffu, rs0, 1);
        rs0 += __shfl_xor_sync(0xffffffffu, rs0, 2);
        rs1 += __shfl_xor_sync(0xffffffffu, rs1, 1);
        rs1 += __shfl_xor_sync(0xffffffffu, rs1, 2);

        lrow0 = lrow0 * alpha0 + rs0;
        lrow1 = lrow1 * alpha1 + rs1;
        mrow0 = mnew0;
        mrow1 = mnew1;
#pragma unroll
        for (int nt = 0; nt < 8; nt++) {
            oacc[nt][0] *= alpha0;
            oacc[nt][1] *= alpha0;
            oacc[nt][2] *= alpha1;
            oacc[nt][3] *= alpha1;
        }

#pragma unroll
        for (int np = 0; np < 4; np++) {
#pragma unroll
            for (int ks = 0; ks < 8; ks++) {
                uint32_t addr = vbuf +
                    ((uint32_t)((np * 16 + brow_off) * VP + ks * 16 + bcol_off) << 1);
                uint32_t h0, h1, h2, h3;
                ldmx4(h0, h1, h2, h3, addr);
                uint32_t bh0[2] = {h0, h1}, bh1[2] = {h2, h3};
                mma16816(oacc[2 * np],     ph[ks], bh0);
                mma16816(oacc[2 * np + 1], ph[ks], bh1);
            }
        }
    }
#undef ATT_LOAD

    float inv0 = 16.f / lrow0;
    float inv1 = 16.f / lrow1;
    const size_t o0 = ((size_t)b * TT + row0) * DM + h * DH + (lane & 3) * 2;
    const size_t o1 = ((size_t)b * TT + row1) * DM + h * DH + (lane & 3) * 2;
#pragma unroll
    for (int nt = 0; nt < 8; nt++) {
        *(uint32_t*)(g_Ah + o0 + nt * 8) =
            packh(oacc[nt][0] * inv0, oacc[nt][1] * inv0);
        *(uint32_t*)(g_Ah + o1 + nt * 8) =
            packh(oacc[nt][2] * inv1, oacc[nt][3] * inv1);
    }
}

// ---------------------------------------------------------------------------
extern "C" void kernel_launch(void* const* d_in, const int* in_sizes, int n_in,
                              void* d_out, int out_size)
{
    const float* x  = (const float*)d_in[0];
    const float* Wq = (const float*)d_in[1];
    const float* Wk = (const float*)d_in[2];
    const float* Wv = (const float*)d_in[3];
    const float* Wo = (const float*)d_in[4];
    float* out = (float*)d_out;

    int8_t *x8h, *x8l, *wc8h, *wc8l;
    half *wo, *ah;
    cudaGetSymbolAddress((void**)&x8h, g_x8h);   cudaGetSymbolAddress((void**)&x8l, g_x8l);
    cudaGetSymbolAddress((void**)&wc8h, g_Wc8h); cudaGetSymbolAddress((void**)&wc8l, g_Wc8l);
    cudaGetSymbolAddress((void**)&wo, g_Wo);
    cudaGetSymbolAddress((void**)&ah, g_Ah);

    cudaFuncSetAttribute(gemm8_qkv, cudaFuncAttributeMaxDynamicSharedMemorySize,
                         GEMM8_SMEM);
    cudaFuncSetAttribute(gemm2_f32, cudaFuncAttributeMaxDynamicSharedMemorySize,
                         GEMM2_SMEM);
    cudaFuncSetAttribute(attn_mma, cudaFuncAttributeMaxDynamicSharedMemorySize,
                         ATTN_SMEM);

    // ---- fused precompute (one launch)
    prep_kernel<<<(N_PREP + 255) / 256, 256>>>(x, Wq, Wk, Wv, Wo);

    // ---- fused QKV projection + RoPE (IMMA, 128x64 tiles, 2 CTAs/SM)
    gemm8_qkv<<<dim3(NC / 64, BT / 128), 256, GEMM8_SMEM>>>(x8h, x8l, wc8h, wc8l);

    // ---- attention (pipelined single-term fp16 HMMA)
    attn_mma<<<dim3(TT / 128, NH, BB), 256, ATTN_SMEM>>>();

    // ---- output projection (single-term fp16, 2 CTAs/SM)
    gemm2_f32<<<dim3(DM / 128, BT / 128), 256, GEMM2_SMEM>>>(ah, wo, out, DM, DM);
}